// round 1
// baseline (speedup 1.0000x reference)
#include <cuda_runtime.h>
#include <cstddef>

// ----------------------------------------------------------------------------
// PrecomputedMetaNet: fp32 baseline
//   h     = relu(X @ W1^T + b1)            [4096,256]
//   coeff = h @ W2^T + b2                  [4096,8]
//   x_{j+1} = x_j + coeff[:,j] * (x_j @ M_j)   (8 sequential steps)
//   out   = x_8 @ Wp^T
// ----------------------------------------------------------------------------

#define BM 128
#define BN 128
#define BK 8

static const int B_ = 4096;
static const int D_ = 1024;
static const int H_ = 256;
static const int T_ = 8;

// scratch (no cudaMalloc allowed)
__device__ float g_h[4096 * 256];
__device__ float g_coeff[4096 * 8];
__device__ float g_buf0[4096 * 1024];
__device__ float g_buf1[4096 * 1024];

// EPI: 0 = plain store, 1 = relu(acc + bias[col]), 2 = A[r,c] + coeff[r,j]*acc
// BT : false = B is [K,N] (NN), true = B is [N,K] (NT, i.e. X @ B^T)
template <bool BT, int EPI>
__global__ __launch_bounds__(256)
void gemm_kernel(const float* __restrict__ A, const float* __restrict__ B,
                 const float* __restrict__ bias,
                 const float* __restrict__ coeff, int cj,
                 float* __restrict__ out, int M, int N, int K)
{
    __shared__ float As[BK][BM + 4];
    __shared__ float Bs[BK][BN + 4];

    const int tid = threadIdx.x;
    const int bm = blockIdx.y * BM;
    const int bn = blockIdx.x * BN;
    const int tx = tid & 15;   // 0..15
    const int ty = tid >> 4;   // 0..15

    float acc[8][8];
#pragma unroll
    for (int i = 0; i < 8; i++)
#pragma unroll
        for (int j = 0; j < 8; j++) acc[i][j] = 0.0f;

    const int a_row = tid >> 1;          // 0..127
    const int a_col = (tid & 1) << 2;    // 0 or 4

    for (int k0 = 0; k0 < K; k0 += BK) {
        // --- load A tile [BM x BK], store transposed As[k][m] ---
        float4 av = *(const float4*)(A + (size_t)(bm + a_row) * K + k0 + a_col);
        As[a_col + 0][a_row] = av.x;
        As[a_col + 1][a_row] = av.y;
        As[a_col + 2][a_row] = av.z;
        As[a_col + 3][a_row] = av.w;

        // --- load B tile into Bs[k][n] ---
        if (!BT) {
            // B is [K,N]: tile rows k0..k0+7, cols bn..bn+127 (coalesced)
            int r = tid >> 5;               // 0..7
            int c = (tid & 31) << 2;        // 0..124
            float4 bv = *(const float4*)(B + (size_t)(k0 + r) * N + bn + c);
            *(float4*)&Bs[r][c] = bv;
        } else {
            // B is [N,K]: read 4 consecutive k for one n, scatter-transpose
            int n  = tid >> 1;              // 0..127
            int kk = (tid & 1) << 2;        // 0 or 4
            float4 bv = *(const float4*)(B + (size_t)(bn + n) * K + k0 + kk);
            Bs[kk + 0][n] = bv.x;
            Bs[kk + 1][n] = bv.y;
            Bs[kk + 2][n] = bv.z;
            Bs[kk + 3][n] = bv.w;
        }
        __syncthreads();

#pragma unroll
        for (int k = 0; k < BK; k++) {
            float a[8], b[8];
            *(float4*)&a[0] = *(const float4*)&As[k][ty * 4];
            *(float4*)&a[4] = *(const float4*)&As[k][64 + ty * 4];
            *(float4*)&b[0] = *(const float4*)&Bs[k][tx * 4];
            *(float4*)&b[4] = *(const float4*)&Bs[k][64 + tx * 4];
#pragma unroll
            for (int i = 0; i < 8; i++)
#pragma unroll
                for (int j = 0; j < 8; j++)
                    acc[i][j] += a[i] * b[j];
        }
        __syncthreads();
    }

    // --- epilogue ---
#pragma unroll
    for (int i = 0; i < 8; i++) {
        int r = bm + ((i < 4) ? (ty * 4 + i) : (64 + ty * 4 + i - 4));
        float cr = 0.0f;
        if (EPI == 2) cr = coeff[r * 8 + cj];
#pragma unroll
        for (int jh = 0; jh < 2; jh++) {
            int c0 = bn + ((jh == 0) ? (tx * 4) : (64 + tx * 4));
            const float* accp = &acc[i][jh * 4];
            float4 v;
            if (EPI == 0) {
                v.x = accp[0]; v.y = accp[1]; v.z = accp[2]; v.w = accp[3];
            } else if (EPI == 1) {
                v.x = fmaxf(accp[0] + bias[c0 + 0], 0.0f);
                v.y = fmaxf(accp[1] + bias[c0 + 1], 0.0f);
                v.z = fmaxf(accp[2] + bias[c0 + 2], 0.0f);
                v.w = fmaxf(accp[3] + bias[c0 + 3], 0.0f);
            } else {
                // step epilogue: out = A[r,c] + cr * acc   (requires K == N)
                float4 base = *(const float4*)(A + (size_t)r * K + c0);
                v.x = base.x + cr * accp[0];
                v.y = base.y + cr * accp[1];
                v.z = base.z + cr * accp[2];
                v.w = base.w + cr * accp[3];
            }
            *(float4*)(out + (size_t)r * N + c0) = v;
        }
    }
}

// coeff[i,t] = dot(h[i,:], W2[t,:]) + b2[t] ; one warp per row
__global__ __launch_bounds__(256)
void coeff_kernel(const float* __restrict__ h, const float* __restrict__ W2,
                  const float* __restrict__ b2, float* __restrict__ coeff)
{
    int w = threadIdx.x >> 5;
    int l = threadIdx.x & 31;
    int row = blockIdx.x * 8 + w;
    const float* hr = h + (size_t)row * 256;

    float acc[8];
#pragma unroll
    for (int t = 0; t < 8; t++) acc[t] = 0.0f;

    for (int k = l; k < 256; k += 32) {
        float hv = hr[k];
#pragma unroll
        for (int t = 0; t < 8; t++)
            acc[t] += hv * W2[t * 256 + k];
    }
#pragma unroll
    for (int t = 0; t < 8; t++) {
#pragma unroll
        for (int o = 16; o > 0; o >>= 1)
            acc[t] += __shfl_xor_sync(0xFFFFFFFFu, acc[t], o);
    }
    if (l == 0) {
#pragma unroll
        for (int t = 0; t < 8; t++)
            coeff[row * 8 + t] = acc[t] + b2[t];
    }
}

extern "C" void kernel_launch(void* const* d_in, const int* in_sizes, int n_in,
                              void* d_out, int out_size)
{
    const float* features = (const float*)d_in[0];
    const float* W1       = (const float*)d_in[1];
    const float* b1       = (const float*)d_in[2];
    const float* W2       = (const float*)d_in[3];
    const float* b2       = (const float*)d_in[4];
    const float* task     = (const float*)d_in[5];
    const float* Wp       = (const float*)d_in[6];
    float* out = (float*)d_out;

    float *h, *coeff, *buf0, *buf1;
    cudaGetSymbolAddress((void**)&h,     g_h);
    cudaGetSymbolAddress((void**)&coeff, g_coeff);
    cudaGetSymbolAddress((void**)&buf0,  g_buf0);
    cudaGetSymbolAddress((void**)&buf1,  g_buf1);

    // metanet hidden: h = relu(X @ W1^T + b1)   [4096 x 256]
    gemm_kernel<true, 1><<<dim3(H_ / BN, B_ / BM), 256>>>(
        features, W1, b1, nullptr, 0, h, B_, H_, D_);

    // coeff = h @ W2^T + b2   [4096 x 8]
    coeff_kernel<<<B_ / 8, 256>>>(h, W2, b2, coeff);

    // 8 sequential soft task-vector steps
    const float* cur = features;
    for (int j = 0; j < T_; j++) {
        float* nxt = (j & 1) ? buf1 : buf0;
        gemm_kernel<false, 2><<<dim3(D_ / BN, B_ / BM), 256>>>(
            cur, task + (size_t)j * D_ * D_, nullptr, coeff, j, nxt, B_, D_, D_);
        cur = nxt;
    }

    // final projection: out = x @ Wp^T
    gemm_kernel<true, 0><<<dim3(D_ / BN, B_ / BM), 256>>>(
        cur, Wp, nullptr, nullptr, 0, out, B_, D_, D_);
}

// round 4
// speedup vs baseline: 4.4222x; 4.4222x over previous
#include <cuda_runtime.h>
#include <cuda_bf16.h>
#include <cstdint>
#include <cstddef>

// ============================================================================
// PrecomputedMetaNet via mma.sync bf16 (sm_103 base ISA; tcgen05 PTX is
// rejected by this harness's ptxas target).
//   h     = relu(X @ W1^T + b1)                 [4096,256]   3-term split-bf16
//   coeff = h @ W2^T + b2                       [4096,8]     fp32 warp GEMV
//   x_{j+1} = x_j + coeff[:,j]*(x_j @ M_j)      8 steps      1-term bf16
//   out   = x_8 @ Wp^T                                        3-term split-bf16
// All GEMMs: D[m,n] = sum_k A[m,k]*B[n,k]; B pre-split to bf16 hi/lo, [N,K].
// ============================================================================

#define B_  4096
#define D_  1024
#define H_  256
#define T_  8

// ---------------- device scratch (no cudaMalloc allowed) ----------------
__device__ __align__(16) __nv_bfloat16 g_task_hi[T_ * D_ * D_];
__device__ __align__(16) __nv_bfloat16 g_w1_hi[H_ * D_];
__device__ __align__(16) __nv_bfloat16 g_w1_lo[H_ * D_];
__device__ __align__(16) __nv_bfloat16 g_wp_hi[D_ * D_];
__device__ __align__(16) __nv_bfloat16 g_wp_lo[D_ * D_];
__device__ __align__(16) float g_h[B_ * H_];
__device__ __align__(16) float g_coeff[B_ * T_];
__device__ __align__(16) float g_buf0[B_ * D_];
__device__ __align__(16) float g_buf1[B_ * D_];

// ---------------- helpers ----------------
__device__ __forceinline__ uint32_t smem_u32(const void* p) {
    uint32_t a;
    asm("{ .reg .u64 t; cvta.to.shared.u64 t, %1; cvt.u32.u64 %0, t; }"
        : "=r"(a) : "l"(p));
    return a;
}

__device__ __forceinline__ void ldsm_x4(uint32_t& r0, uint32_t& r1,
                                        uint32_t& r2, uint32_t& r3, uint32_t addr) {
    asm volatile("ldmatrix.sync.aligned.m8n8.x4.shared.b16 {%0,%1,%2,%3}, [%4];"
                 : "=r"(r0), "=r"(r1), "=r"(r2), "=r"(r3) : "r"(addr));
}

__device__ __forceinline__ void mma_bf16(float* d, const uint32_t* a, const uint32_t* b) {
    asm volatile(
        "mma.sync.aligned.m16n8k16.row.col.f32.bf16.bf16.f32 "
        "{%0,%1,%2,%3},{%4,%5,%6,%7},{%8,%9},{%0,%1,%2,%3};"
        : "+f"(d[0]), "+f"(d[1]), "+f"(d[2]), "+f"(d[3])
        : "r"(a[0]), "r"(a[1]), "r"(a[2]), "r"(a[3]), "r"(b[0]), "r"(b[1]));
}

__device__ __forceinline__ uint32_t f2bf2(float x, float y) {
    __nv_bfloat162 t = __floats2bfloat162_rn(x, y);   // x -> low half
    return *reinterpret_cast<uint32_t*>(&t);
}

// ============================================================================
// GEMM: BM=128, BN=128, BK=32. 256 threads, 8 warps (4 along M x 2 along N),
// warp tile 32x64 = 2 m16 x 8 n8 mma tiles. Smem rows pitched 80B
// (conflict-free ldmatrix). Register prefetch of next K-tile.
// NTERMS: 1 = hi*hi only; 3 = hi*hi + lo*hi + hi*lo.
// EPI: 0 plain; 1 relu(acc+bias[col]); 2 A[r,c] + coeff[r,cj]*acc (K==N).
// ============================================================================
template <int NTERMS, int EPI>
__global__ __launch_bounds__(256)
void mm_kernel(const float* __restrict__ A,
               const __nv_bfloat16* __restrict__ Bhi,
               const __nv_bfloat16* __restrict__ Blo,
               const float* __restrict__ bias,
               const float* __restrict__ coeff, int cj,
               float* __restrict__ out, int M, int N, int K)
{
    constexpr int PITCH = 80;                       // bytes per 32-bf16 row (+16B pad)
    constexpr int TILEB = 128 * PITCH;              // 10240 bytes per operand tile
    __shared__ __align__(16) char sAh[TILEB];
    __shared__ __align__(16) char sBh[TILEB];
    __shared__ __align__(16) char sAl[NTERMS == 3 ? TILEB : 16];
    __shared__ __align__(16) char sBl[NTERMS == 3 ? TILEB : 16];

    const int tid  = threadIdx.x;
    const int wid  = tid >> 5;
    const int lane = tid & 31;
    const int warp_m = (wid & 3) * 32;
    const int warp_n = (wid >> 2) * 64;
    const int bm = blockIdx.y * 128;
    const int bn = blockIdx.x * 128;

    const uint32_t suAh = smem_u32(sAh);
    const uint32_t suBh = smem_u32(sBh);
    const uint32_t suAl = smem_u32(sAl);
    const uint32_t suBl = smem_u32(sBl);

    // per-thread ldmatrix address components
    const uint32_t a_off = (lane & 15) * PITCH + ((lane >> 4) & 1) * 16;
    const uint32_t b_off = ((lane & 7) + ((lane >> 4) & 1) * 8) * PITCH + ((lane >> 3) & 1) * 16;

    float acc[2][8][4];
#pragma unroll
    for (int mt = 0; mt < 2; mt++)
#pragma unroll
        for (int nt = 0; nt < 8; nt++)
#pragma unroll
            for (int q = 0; q < 4; q++) acc[mt][nt][q] = 0.0f;

    // prefetch registers
    float4 ag[4];
    uint4  bgh[2], bgl[2];
    const int ar = tid >> 3;            // A row within 32-row group (0..31)
    const int af = tid & 7;             // float4 index within 32-float row

    const int NTILES = K >> 5;

    // ---- load tile 0 ----
#pragma unroll
    for (int it = 0; it < 4; it++) {
        int r = it * 32 + ar;
        ag[it] = *(const float4*)(A + (size_t)(bm + r) * K + af * 4);
    }
    // B tile: 128 n-rows x 32 bf16 = 4 x 16B chunks per row = 512 chunks
#pragma unroll
    for (int it = 0; it < 2; it++) {
        int idx = it * 256 + tid;
        int n = idx >> 2, k16 = idx & 3;
        bgh[it] = *(const uint4*)(Bhi + (size_t)(bn + n) * K + k16 * 8);
        if (NTERMS == 3)
            bgl[it] = *(const uint4*)(Blo + (size_t)(bn + n) * K + k16 * 8);
    }

    for (int t = 0; t < NTILES; t++) {
        // ---- store current tile to smem ----
#pragma unroll
        for (int it = 0; it < 4; it++) {
            int r = it * 32 + ar;
            float4 v = ag[it];
            uint32_t h0 = f2bf2(v.x, v.y), h1 = f2bf2(v.z, v.w);
            uint32_t off = r * PITCH + af * 8;
            *(uint2*)(sAh + off) = make_uint2(h0, h1);
            if (NTERMS == 3) {
                __nv_bfloat162 hh0 = *reinterpret_cast<__nv_bfloat162*>(&h0);
                __nv_bfloat162 hh1 = *reinterpret_cast<__nv_bfloat162*>(&h1);
                uint32_t l0 = f2bf2(v.x - __bfloat162float(hh0.x),
                                    v.y - __bfloat162float(hh0.y));
                uint32_t l1 = f2bf2(v.z - __bfloat162float(hh1.x),
                                    v.w - __bfloat162float(hh1.y));
                *(uint2*)(sAl + off) = make_uint2(l0, l1);
            }
        }
#pragma unroll
        for (int it = 0; it < 2; it++) {
            int idx = it * 256 + tid;
            int n = idx >> 2, k16 = idx & 3;
            uint32_t off = n * PITCH + k16 * 16;
            *(uint4*)(sBh + off) = bgh[it];
            if (NTERMS == 3) *(uint4*)(sBl + off) = bgl[it];
        }
        __syncthreads();

        // ---- prefetch next tile ----
        if (t + 1 < NTILES) {
            int k0 = (t + 1) << 5;
#pragma unroll
            for (int it = 0; it < 4; it++) {
                int r = it * 32 + ar;
                ag[it] = *(const float4*)(A + (size_t)(bm + r) * K + k0 + af * 4);
            }
#pragma unroll
            for (int it = 0; it < 2; it++) {
                int idx = it * 256 + tid;
                int n = idx >> 2, k16 = idx & 3;
                bgh[it] = *(const uint4*)(Bhi + (size_t)(bn + n) * K + k0 + k16 * 8);
                if (NTERMS == 3)
                    bgl[it] = *(const uint4*)(Blo + (size_t)(bn + n) * K + k0 + k16 * 8);
            }
        }

        // ---- compute: 2 k-steps of 16 ----
#pragma unroll
        for (int ks = 0; ks < 2; ks++) {
            uint32_t ah[2][4], al[2][4];
#pragma unroll
            for (int mt = 0; mt < 2; mt++) {
                uint32_t base = (warp_m + mt * 16) * PITCH + a_off + ks * 32;
                ldsm_x4(ah[mt][0], ah[mt][1], ah[mt][2], ah[mt][3], suAh + base);
                if (NTERMS == 3)
                    ldsm_x4(al[mt][0], al[mt][1], al[mt][2], al[mt][3], suAl + base);
            }
            uint32_t bh[8][2], bl[8][2];
#pragma unroll
            for (int ng = 0; ng < 4; ng++) {
                uint32_t base = (warp_n + ng * 16) * PITCH + b_off + ks * 32;
                ldsm_x4(bh[2 * ng][0], bh[2 * ng][1], bh[2 * ng + 1][0], bh[2 * ng + 1][1],
                        suBh + base);
                if (NTERMS == 3)
                    ldsm_x4(bl[2 * ng][0], bl[2 * ng][1], bl[2 * ng + 1][0], bl[2 * ng + 1][1],
                            suBl + base);
            }
#pragma unroll
            for (int mt = 0; mt < 2; mt++)
#pragma unroll
                for (int nt = 0; nt < 8; nt++) {
                    mma_bf16(acc[mt][nt], ah[mt], bh[nt]);
                    if (NTERMS == 3) {
                        mma_bf16(acc[mt][nt], al[mt], bh[nt]);
                        mma_bf16(acc[mt][nt], ah[mt], bl[nt]);
                    }
                }
        }
        __syncthreads();
    }

    // ---- epilogue ----
#pragma unroll
    for (int mt = 0; mt < 2; mt++) {
        int row0 = bm + warp_m + mt * 16 + (lane >> 2);
        int row1 = row0 + 8;
        float cr0 = 0.0f, cr1 = 0.0f;
        if (EPI == 2) {
            cr0 = coeff[row0 * T_ + cj];
            cr1 = coeff[row1 * T_ + cj];
        }
#pragma unroll
        for (int nt = 0; nt < 8; nt++) {
            int col = bn + warp_n + nt * 8 + (lane & 3) * 2;
            float2 v0 = make_float2(acc[mt][nt][0], acc[mt][nt][1]);
            float2 v1 = make_float2(acc[mt][nt][2], acc[mt][nt][3]);
            if (EPI == 1) {
                float2 bv = *(const float2*)(bias + col);
                v0.x = fmaxf(v0.x + bv.x, 0.0f);
                v0.y = fmaxf(v0.y + bv.y, 0.0f);
                v1.x = fmaxf(v1.x + bv.x, 0.0f);
                v1.y = fmaxf(v1.y + bv.y, 0.0f);
            } else if (EPI == 2) {
                float2 b0 = *(const float2*)(A + (size_t)row0 * K + col);
                float2 b1 = *(const float2*)(A + (size_t)row1 * K + col);
                v0.x = b0.x + cr0 * v0.x;
                v0.y = b0.y + cr0 * v0.y;
                v1.x = b1.x + cr1 * v1.x;
                v1.y = b1.y + cr1 * v1.y;
            }
            *(float2*)(out + (size_t)row0 * N + col) = v0;
            *(float2*)(out + (size_t)row1 * N + col) = v1;
        }
    }
}

// ============================================================================
// pre-pass kernels
// ============================================================================
__global__ void convert_split(const float* __restrict__ in,
                              __nv_bfloat16* __restrict__ hi,
                              __nv_bfloat16* __restrict__ lo, int n)
{
    int i = blockIdx.x * blockDim.x + threadIdx.x;
    if (i < n) {
        float v = in[i];
        __nv_bfloat16 h = __float2bfloat16_rn(v);
        hi[i] = h;
        lo[i] = __float2bfloat16_rn(v - __bfloat162float(h));
    }
}

// task_mats [T][K][N] -> [T][N][K] bf16 hi
__global__ void transpose_hi(const float* __restrict__ in,
                             __nv_bfloat16* __restrict__ hi)
{
    __shared__ float tile[32][33];
    int j = blockIdx.z;
    const float* src = in + (size_t)j * D_ * D_;
    int n0 = blockIdx.x * 32, k0 = blockIdx.y * 32;
    int tx = threadIdx.x, ty = threadIdx.y;
#pragma unroll
    for (int i = 0; i < 32; i += 8)
        tile[ty + i][tx] = src[(size_t)(k0 + ty + i) * D_ + n0 + tx];
    __syncthreads();
#pragma unroll
    for (int i = 0; i < 32; i += 8) {
        float v = tile[tx][ty + i];
        size_t o = (size_t)j * D_ * D_ + (size_t)(n0 + ty + i) * D_ + k0 + tx;
        hi[o] = __float2bfloat16_rn(v);
    }
}

// coeff[i,t] = dot(h[i,:], W2[t,:]) + b2[t] ; one warp per row
__global__ __launch_bounds__(256)
void coeff_kernel(const float* __restrict__ h, const float* __restrict__ W2,
                  const float* __restrict__ b2, float* __restrict__ coeff)
{
    int w = threadIdx.x >> 5;
    int l = threadIdx.x & 31;
    int row = blockIdx.x * 8 + w;
    const float* hr = h + (size_t)row * H_;

    float acc[8];
#pragma unroll
    for (int t = 0; t < 8; t++) acc[t] = 0.0f;
    for (int k = l; k < H_; k += 32) {
        float hv = hr[k];
#pragma unroll
        for (int t = 0; t < 8; t++) acc[t] += hv * W2[t * H_ + k];
    }
#pragma unroll
    for (int t = 0; t < 8; t++)
#pragma unroll
        for (int o = 16; o > 0; o >>= 1)
            acc[t] += __shfl_xor_sync(0xFFFFFFFFu, acc[t], o);
    if (l == 0)
#pragma unroll
        for (int t = 0; t < 8; t++)
            coeff[row * 8 + t] = acc[t] + b2[t];
}

// ============================================================================
extern "C" void kernel_launch(void* const* d_in, const int* in_sizes, int n_in,
                              void* d_out, int out_size)
{
    const float* features = (const float*)d_in[0];
    const float* W1       = (const float*)d_in[1];
    const float* b1       = (const float*)d_in[2];
    const float* W2       = (const float*)d_in[3];
    const float* b2       = (const float*)d_in[4];
    const float* task     = (const float*)d_in[5];
    const float* Wp       = (const float*)d_in[6];
    float* out = (float*)d_out;

    __nv_bfloat16 *thi, *w1hi, *w1lo, *wphi, *wplo;
    float *h, *coeff, *buf0, *buf1;
    cudaGetSymbolAddress((void**)&thi,  g_task_hi);
    cudaGetSymbolAddress((void**)&w1hi, g_w1_hi);
    cudaGetSymbolAddress((void**)&w1lo, g_w1_lo);
    cudaGetSymbolAddress((void**)&wphi, g_wp_hi);
    cudaGetSymbolAddress((void**)&wplo, g_wp_lo);
    cudaGetSymbolAddress((void**)&h,     g_h);
    cudaGetSymbolAddress((void**)&coeff, g_coeff);
    cudaGetSymbolAddress((void**)&buf0,  g_buf0);
    cudaGetSymbolAddress((void**)&buf1,  g_buf1);

    // ---- pre-pass: split weights to bf16 (hi/lo), transpose task mats (hi) ----
    convert_split<<<(H_ * D_ + 255) / 256, 256>>>(W1, w1hi, w1lo, H_ * D_);
    convert_split<<<(D_ * D_ + 255) / 256, 256>>>(Wp, wphi, wplo, D_ * D_);
    transpose_hi<<<dim3(D_ / 32, D_ / 32, T_), dim3(32, 8)>>>(task, thi);

    // ---- metanet hidden: h = relu(X @ W1^T + b1), 3-term ----
    mm_kernel<3, 1><<<dim3(H_ / 128, B_ / 128), 256>>>(
        features, w1hi, w1lo, b1, nullptr, 0, h, B_, H_, D_);

    // ---- coeff = h @ W2^T + b2 ----
    coeff_kernel<<<B_ / 8, 256>>>(h, W2, b2, coeff);

    // ---- 8 sequential soft task-vector steps, 1-term bf16 ----
    const float* cur = features;
    for (int j = 0; j < T_; ++j) {
        float* nxt = (j & 1) ? buf1 : buf0;
        mm_kernel<1, 2><<<dim3(D_ / 128, B_ / 128), 256>>>(
            cur, thi + (size_t)j * D_ * D_, nullptr, nullptr, coeff, j,
            nxt, B_, D_, D_);
        cur = nxt;
    }

    // ---- final projection: out = x @ Wp^T, 3-term ----
    mm_kernel<3, 0><<<dim3(D_ / 128, B_ / 128), 256>>>(
        cur, wphi, wplo, nullptr, nullptr, 0, out, B_, D_, D_);
}